// round 3
// baseline (speedup 1.0000x reference)
#include <cuda_runtime.h>
#include <cuda_bf16.h>

// Reference analysis:
//   OD        = tanh(...)            -> fp32 values in (-1, 1], saturating at exactly 1.0f
//   adjacency = where(OD > 1.0, OD, 0)  (strict >) -> identically 0 everywhere
//   output[b, t, 0] = adjacency[cur, nxt]           -> identically 0
// The entire GAT stack / OD matrix / gumbel walks are dead code w.r.t. the
// output. The correct output is exactly zeros of shape [256, 199, 1].
// d_out is poisoned to 0xAA before timing, so we must zero it on every call.

__global__ void zero_out_kernel(float* __restrict__ out, int n) {
    int i = blockIdx.x * blockDim.x + threadIdx.x;
    int n4 = n >> 2;  // number of float4 chunks
    if (i < n4) {
        reinterpret_cast<float4*>(out)[i] = make_float4(0.f, 0.f, 0.f, 0.f);
    }
    // scalar tail (n % 4 elements), handled by the first few threads
    int tail_start = n4 << 2;
    int t = tail_start + i;
    if (i < (n - tail_start)) {
        out[t] = 0.f;
    }
}

extern "C" void kernel_launch(void* const* d_in, const int* in_sizes, int n_in,
                              void* d_out, int out_size) {
    (void)d_in; (void)in_sizes; (void)n_in;
    float* out = (float*)d_out;
    int n4 = (out_size + 3) >> 2;
    int threads = 128;
    int blocks = (n4 + threads - 1) / threads;
    if (blocks < 1) blocks = 1;
    zero_out_kernel<<<blocks, threads>>>(out, out_size);
}

// round 4
// speedup vs baseline: 1.1184x; 1.1184x over previous
#include <cuda_runtime.h>
#include <cuda_bf16.h>

// Reference analysis (unchanged from R2, verified rel_err=0.0):
//   OD        = tanh(...)               -> fp32 in (-1, 1], saturates at exactly 1.0f
//   adjacency = where(OD > 1.0, OD, 0)  -> strict '>' vs tanh output: identically 0
//   output[b, t, 0] = adjacency[cur, nxt] -> identically 0 for all [256, 199, 1]
// Entire GAT stack / OD matrix / gumbel walks are dead code w.r.t. the output.
//
// R3 change: swap the SM zero-fill kernel for a cudaMemsetAsync. This captures
// as a graph memset node (copy-engine path) — no CTA scheduling / SM dispatch,
// which was 100% of the previous kernel's 3.4µs cost (DRAM=0.0%, occ=8.7%:
// pure launch floor). Memset is graph-capturable and allocation-free.

extern "C" void kernel_launch(void* const* d_in, const int* in_sizes, int n_in,
                              void* d_out, int out_size) {
    (void)d_in; (void)in_sizes; (void)n_in;
    // Output dtype is float32; zeroing bytes gives bit-exact 0.0f.
    cudaMemsetAsync(d_out, 0, (size_t)out_size * sizeof(float));
}